// round 1
// baseline (speedup 1.0000x reference)
#include <cuda_runtime.h>
#include <cuda_bf16.h>

// Merged multi-hot embedding bag, sum pooling.
// B=32768, NT=26 tables, 214 packed index columns, DIM=128 fp32.
// Output: [B, 26*128] fp32.

#define BATCH 32768
#define NT 26
#define TOTAL_COLS 214
#define DIM 128

// per-table hot counts and their starting column in the packed [B,214] indices
__constant__ int c_hots[NT] = {3,2,1,2,6,1,1,1,1,7,3,8,1,6,9,5,1,1,1,12,100,27,10,3,1,1};
__constant__ int c_hotstart[NT] = {0,3,5,6,8,14,15,16,17,18,25,28,36,37,43,52,57,58,59,60,72,172,199,209,212,213};

__global__ __launch_bounds__(256, 8)
void merged_embed_bag_kernel(const int* __restrict__ indices,
                             const float* __restrict__ weights,
                             float* __restrict__ out)
{
    // one warp per (b, t) segment
    const int warps_per_block = blockDim.x >> 5;
    const long long gwarp = (long long)blockIdx.x * warps_per_block + (threadIdx.x >> 5);
    const long long total_warps = (long long)BATCH * NT;
    if (gwarp >= total_warps) return;

    const int t = (int)(gwarp % NT);
    const int b = (int)(gwarp / NT);
    const int lane = threadIdx.x & 31;

    const int hots = c_hots[t];
    const int hstart = c_hotstart[t];
    const int* idxp = indices + (long long)b * TOTAL_COLS + hstart;

    float4 acc = make_float4(0.f, 0.f, 0.f, 0.f);

    int h = 0;
    // 2-way software pipelining: two independent row loads in flight
    for (; h + 1 < hots; h += 2) {
        const int i0 = __ldg(idxp + h);
        const int i1 = __ldg(idxp + h + 1);
        const float4 a = __ldg((const float4*)(weights + (long long)i0 * DIM) + lane);
        const float4 c = __ldg((const float4*)(weights + (long long)i1 * DIM) + lane);
        acc.x += a.x + c.x;
        acc.y += a.y + c.y;
        acc.z += a.z + c.z;
        acc.w += a.w + c.w;
    }
    if (h < hots) {
        const int i0 = __ldg(idxp + h);
        const float4 a = __ldg((const float4*)(weights + (long long)i0 * DIM) + lane);
        acc.x += a.x;
        acc.y += a.y;
        acc.z += a.z;
        acc.w += a.w;
    }

    // out[b, t*128 + lane*4 .. +3], streaming store (evict-first: keep L2 for weights)
    float4* outp = (float4*)(out + (long long)b * (NT * DIM) + t * DIM) + lane;
    __stcs(outp, acc);
}

extern "C" void kernel_launch(void* const* d_in, const int* in_sizes, int n_in,
                              void* d_out, int out_size)
{
    // Identify inputs by size (indices: 32768*214 int32; weights: 1,995,000*128 fp32)
    const int* indices = nullptr;
    const float* weights = nullptr;
    const long long idx_elems = (long long)BATCH * TOTAL_COLS;
    for (int i = 0; i < n_in; i++) {
        if ((long long)in_sizes[i] == idx_elems) indices = (const int*)d_in[i];
        else weights = (const float*)d_in[i];
    }

    float* out = (float*)d_out;

    const int threads = 256;
    const int warps_per_block = threads / 32;
    const long long total_warps = (long long)BATCH * NT;
    const int blocks = (int)((total_warps + warps_per_block - 1) / warps_per_block);

    merged_embed_bag_kernel<<<blocks, threads>>>(indices, weights, out);
}

// round 2
// speedup vs baseline: 1.0553x; 1.0553x over previous
#include <cuda_runtime.h>
#include <cuda_bf16.h>

// Merged multi-hot embedding bag, sum pooling.
// B=32768, NT=26 tables, 214 packed index columns, DIM=128 fp32.
// Output: [B, 26*128] fp32.
//
// Job layout: 16 warp-jobs per sample:
//   jobs 0..14 : the 15 multi-hot tables (hots >= 2), one warp each
//   job  15    : all 11 singleton tables fused into one warp

#define BATCH 32768
#define NT 26
#define TOTAL_COLS 214
#define DIM 128
#define NJOBS 16

// multi-hot tables: table id, hot count, start column
__constant__ int c_mt[15] = {0,1,3,4,9,10,11,13,14,15,19,20,21,22,23};
__constant__ int c_mh[15] = {3,2,2,6,7,3,8,6,9,5,12,100,27,10,3};
__constant__ int c_ms[15] = {0,3,6,8,18,25,28,37,43,52,60,72,172,199,209};
// singleton tables: packed column per lane
__constant__ int c_sc[11] = {5,14,15,16,17,36,57,58,59,212,213};

#define LOAD4_ACC(i0,i1,i2,i3) do {                                              \
    float4 a0 = __ldg((const float4*)(weights + (long long)(i0)*DIM) + lane);    \
    float4 a1 = __ldg((const float4*)(weights + (long long)(i1)*DIM) + lane);    \
    float4 a2 = __ldg((const float4*)(weights + (long long)(i2)*DIM) + lane);    \
    float4 a3 = __ldg((const float4*)(weights + (long long)(i3)*DIM) + lane);    \
    acc.x += (a0.x + a1.x) + (a2.x + a3.x);                                      \
    acc.y += (a0.y + a1.y) + (a2.y + a3.y);                                      \
    acc.z += (a0.z + a1.z) + (a2.z + a3.z);                                      \
    acc.w += (a0.w + a1.w) + (a2.w + a3.w);                                      \
} while (0)

#define LOAD1_ACC(i0) do {                                                       \
    float4 a0 = __ldg((const float4*)(weights + (long long)(i0)*DIM) + lane);    \
    acc.x += a0.x; acc.y += a0.y; acc.z += a0.z; acc.w += a0.w;                  \
} while (0)

__global__ __launch_bounds__(256)
void merged_embed_bag_kernel(const int* __restrict__ indices,
                             const float* __restrict__ weights,
                             float* __restrict__ out)
{
    const int gwarp = blockIdx.x * (blockDim.x >> 5) + (threadIdx.x >> 5);
    const int lane  = threadIdx.x & 31;
    const int b = gwarp >> 4;          // sample
    const int j = gwarp & (NJOBS - 1); // job within sample
    if (b >= BATCH) return;

    const int* rowidx = indices + (long long)b * TOTAL_COLS;
    float* orow = out + (long long)b * (NT * DIM);

    if (j < 15) {
        // ---- multi-hot table job ----
        const int t = c_mt[j];
        const int h = c_mh[j];
        const int s = c_ms[j];
        float4 acc = make_float4(0.f, 0.f, 0.f, 0.f);

        if (h <= 32) {
            // one coalesced index load, broadcast via shfl
            int iv = 0;
            if (lane < h) iv = __ldg(rowidx + s + lane);
            int k = 0;
            for (; k + 4 <= h; k += 4) {
                int i0 = __shfl_sync(0xffffffffu, iv, k);
                int i1 = __shfl_sync(0xffffffffu, iv, k + 1);
                int i2 = __shfl_sync(0xffffffffu, iv, k + 2);
                int i3 = __shfl_sync(0xffffffffu, iv, k + 3);
                LOAD4_ACC(i0, i1, i2, i3);
            }
            for (; k < h; k++) {
                int i0 = __shfl_sync(0xffffffffu, iv, k);
                LOAD1_ACC(i0);
            }
        } else {
            // table 20: h == 100 = 3*32 + 4; process 32 indices per round
            #pragma unroll
            for (int r = 0; r < 4; r++) {
                const int cnt = (r < 3) ? 32 : 4;
                int iv = 0;
                if (lane < cnt) iv = __ldg(rowidx + s + r * 32 + lane);
                int k = 0;
                for (; k + 4 <= cnt; k += 4) {
                    int i0 = __shfl_sync(0xffffffffu, iv, k);
                    int i1 = __shfl_sync(0xffffffffu, iv, k + 1);
                    int i2 = __shfl_sync(0xffffffffu, iv, k + 2);
                    int i3 = __shfl_sync(0xffffffffu, iv, k + 3);
                    LOAD4_ACC(i0, i1, i2, i3);
                }
                for (; k < cnt; k++) {
                    int i0 = __shfl_sync(0xffffffffu, iv, k);
                    LOAD1_ACC(i0);
                }
            }
        }
        __stcs((float4*)(orow + t * DIM) + lane, acc);
    } else {
        // ---- fused singleton job: 11 independent copy lookups ----
        int iv = 0;
        if (lane < 11) iv = __ldg(rowidx + c_sc[lane]);

        // group 0: tables 2, 5, 6, 7  (shfl lanes 0..3)
        {
            int i0 = __shfl_sync(0xffffffffu, iv, 0);
            int i1 = __shfl_sync(0xffffffffu, iv, 1);
            int i2 = __shfl_sync(0xffffffffu, iv, 2);
            int i3 = __shfl_sync(0xffffffffu, iv, 3);
            float4 a0 = __ldg((const float4*)(weights + (long long)i0 * DIM) + lane);
            float4 a1 = __ldg((const float4*)(weights + (long long)i1 * DIM) + lane);
            float4 a2 = __ldg((const float4*)(weights + (long long)i2 * DIM) + lane);
            float4 a3 = __ldg((const float4*)(weights + (long long)i3 * DIM) + lane);
            __stcs((float4*)(orow +  2 * DIM) + lane, a0);
            __stcs((float4*)(orow +  5 * DIM) + lane, a1);
            __stcs((float4*)(orow +  6 * DIM) + lane, a2);
            __stcs((float4*)(orow +  7 * DIM) + lane, a3);
        }
        // group 1: tables 8, 12, 16, 17  (shfl lanes 4..7)
        {
            int i0 = __shfl_sync(0xffffffffu, iv, 4);
            int i1 = __shfl_sync(0xffffffffu, iv, 5);
            int i2 = __shfl_sync(0xffffffffu, iv, 6);
            int i3 = __shfl_sync(0xffffffffu, iv, 7);
            float4 a0 = __ldg((const float4*)(weights + (long long)i0 * DIM) + lane);
            float4 a1 = __ldg((const float4*)(weights + (long long)i1 * DIM) + lane);
            float4 a2 = __ldg((const float4*)(weights + (long long)i2 * DIM) + lane);
            float4 a3 = __ldg((const float4*)(weights + (long long)i3 * DIM) + lane);
            __stcs((float4*)(orow +  8 * DIM) + lane, a0);
            __stcs((float4*)(orow + 12 * DIM) + lane, a1);
            __stcs((float4*)(orow + 16 * DIM) + lane, a2);
            __stcs((float4*)(orow + 17 * DIM) + lane, a3);
        }
        // group 2: tables 18, 24, 25  (shfl lanes 8..10)
        {
            int i0 = __shfl_sync(0xffffffffu, iv, 8);
            int i1 = __shfl_sync(0xffffffffu, iv, 9);
            int i2 = __shfl_sync(0xffffffffu, iv, 10);
            float4 a0 = __ldg((const float4*)(weights + (long long)i0 * DIM) + lane);
            float4 a1 = __ldg((const float4*)(weights + (long long)i1 * DIM) + lane);
            float4 a2 = __ldg((const float4*)(weights + (long long)i2 * DIM) + lane);
            __stcs((float4*)(orow + 18 * DIM) + lane, a0);
            __stcs((float4*)(orow + 24 * DIM) + lane, a1);
            __stcs((float4*)(orow + 25 * DIM) + lane, a2);
        }
    }
}

extern "C" void kernel_launch(void* const* d_in, const int* in_sizes, int n_in,
                              void* d_out, int out_size)
{
    const int* indices = nullptr;
    const float* weights = nullptr;
    const long long idx_elems = (long long)BATCH * TOTAL_COLS;
    for (int i = 0; i < n_in; i++) {
        if ((long long)in_sizes[i] == idx_elems) indices = (const int*)d_in[i];
        else weights = (const float*)d_in[i];
    }
    float* out = (float*)d_out;

    const int threads = 256;
    const int warps_per_block = threads / 32;
    const long long total_warps = (long long)BATCH * NJOBS;  // 524288
    const int blocks = (int)((total_warps + warps_per_block - 1) / warps_per_block);

    merged_embed_bag_kernel<<<blocks, threads>>>(indices, weights, out);
}